// round 3
// baseline (speedup 1.0000x reference)
#include <cuda_runtime.h>

#define N_NODES 100000
#define N_EDGES 600000
#define C 128

// ---------------- scratch (static device globals; no runtime allocation) ----
__device__ __align__(16) float g_W[C * C];                    // evolved GCN weight
__device__ float g_dinv[N_NODES];                             // weighted deg -> dinv
__device__ int   g_cnt[N_NODES];                              // in-degree count / fill cursor
__device__ int   g_off[N_NODES + 1];                          // CSR offsets
__device__ int   g_csr_row[N_EDGES];                          // CSR: source node per slot
__device__ float g_csr_norm[N_EDGES];                         // CSR: norm per slot
__device__ __align__(16) float g_xagg[(size_t)N_NODES * C];   // aggregated x (pre-GEMM)
__device__ int   g_is64;                                      // edge_index dtype flag

// ---------------- 0. detect edge_index width (int32 vs int64) ---------------
// For int64 (values < 2^31) every odd 32-bit word is a zero high-half.
// For int32 the odd words are node indices (nonzero w.p. 1 - 1e-5 each).
__global__ void detect_kernel(const unsigned* __restrict__ ei_w) {
    int nz = 0;
    for (int i = threadIdx.x; i < 512; i += 32)
        if (ei_w[2 * i + 1] != 0u) nz++;
    #pragma unroll
    for (int o = 16; o > 0; o >>= 1) nz += __shfl_down_sync(0xffffffffu, nz, o);
    if (threadIdx.x == 0) g_is64 = (nz == 0) ? 1 : 0;
}

__device__ __forceinline__ int load_idx(const void* ei, long long pos, int is64) {
    return is64 ? (int)((const long long*)ei)[pos] : ((const int*)ei)[pos];
}

// ---------------- 1. GRU evolution of W0 (gate order r,z,n) -----------------
__global__ void gru_kernel(const float* __restrict__ W0,
                           const float* __restrict__ Wih,
                           const float* __restrict__ Whh,
                           const float* __restrict__ bih,
                           const float* __restrict__ bhh) {
    __shared__ float w0row[C];
    int i = blockIdx.x;      // row of W0 (batch dim of GRU)
    int t = threadIdx.x;     // column within each gate
    w0row[t] = W0[i * C + t];
    __syncthreads();

    float gir = bih[t], giz = bih[t + C], gin = bih[t + 2 * C];
    float ghr = bhh[t], ghz = bhh[t + C], ghn = bhh[t + 2 * C];
    const float* wr = Wih + (size_t)t * C;
    const float* wz = Wih + (size_t)(t + C) * C;
    const float* wn = Wih + (size_t)(t + 2 * C) * C;
    const float* hr = Whh + (size_t)t * C;
    const float* hz = Whh + (size_t)(t + C) * C;
    const float* hn = Whh + (size_t)(t + 2 * C) * C;
    #pragma unroll 4
    for (int k = 0; k < C; k++) {
        float a = w0row[k];
        gir += a * wr[k]; giz += a * wz[k]; gin += a * wn[k];
        ghr += a * hr[k]; ghz += a * hz[k]; ghn += a * hn[k];
    }
    float r    = 1.0f / (1.0f + expf(-(gir + ghr)));
    float z    = 1.0f / (1.0f + expf(-(giz + ghz)));
    float cand = tanhf(gin + r * ghn);
    g_W[i * C + t] = (1.0f - z) * cand + z * w0row[t];
}

// ---------------- 2. degree init + count ------------------------------------
__global__ void deg_init() {
    int i = blockIdx.x * blockDim.x + threadIdx.x;
    if (i < N_NODES) { g_dinv[i] = 1.0f; g_cnt[i] = 0; }   // self-loop weight
}

__global__ void count_kernel(const void* __restrict__ ei,
                             const float* __restrict__ ew) {
    int e = blockIdx.x * blockDim.x + threadIdx.x;
    if (e < N_EDGES) {
        int is64 = g_is64;
        int c = load_idx(ei, (long long)N_EDGES + e, is64);   // target
        atomicAdd(&g_dinv[c], ew[e]);    // weighted degree
        atomicAdd(&g_cnt[c], 1);         // in-degree for CSR
    }
}

__global__ void dinv_kernel() {
    int i = blockIdx.x * blockDim.x + threadIdx.x;
    if (i < N_NODES) g_dinv[i] = rsqrtf(g_dinv[i]);   // deg >= 1 always (self-loop)
}

// ---------------- 3. single-block exclusive scan of counts -> offsets -------
__global__ void scan_kernel() {     // <<<1, 1024>>>
    __shared__ int warpsum[32];
    __shared__ int carry_s;
    const int tid = threadIdx.x;
    const int lane = tid & 31, wid = tid >> 5;
    if (tid == 0) carry_s = 0;
    __syncthreads();
    for (int base = 0; base < N_NODES; base += 1024) {
        int i = base + tid;
        int v = (i < N_NODES) ? g_cnt[i] : 0;
        int incl = v;
        #pragma unroll
        for (int o = 1; o < 32; o <<= 1) {
            int t = __shfl_up_sync(0xffffffffu, incl, o);
            if (lane >= o) incl += t;
        }
        if (lane == 31) warpsum[wid] = incl;
        __syncthreads();
        if (wid == 0) {
            int ws = warpsum[lane];
            int wincl = ws;
            #pragma unroll
            for (int o = 1; o < 32; o <<= 1) {
                int t = __shfl_up_sync(0xffffffffu, wincl, o);
                if (lane >= o) wincl += t;
            }
            warpsum[lane] = wincl - ws;   // exclusive warp offset
        }
        __syncthreads();
        int excl = carry_s + warpsum[wid] + incl - v;
        if (i < N_NODES) { g_off[i] = excl; g_cnt[i] = 0; }   // zero cursor for fill
        __syncthreads();                  // everyone has consumed carry_s
        if (tid == 1023) carry_s = excl + v;   // chunk total added to carry
        __syncthreads();
    }
    if (tid == 0) g_off[N_NODES] = N_EDGES;
}

// ---------------- 4. CSR fill (row + norm, contiguous per target) -----------
__global__ void fill_kernel(const void* __restrict__ ei,
                            const float* __restrict__ ew) {
    int e = blockIdx.x * blockDim.x + threadIdx.x;
    if (e < N_EDGES) {
        int is64 = g_is64;
        int r = load_idx(ei, e, is64);
        int c = load_idx(ei, (long long)N_EDGES + e, is64);
        float nv = g_dinv[r] * ew[e] * g_dinv[c];
        int pos = g_off[c] + atomicAdd(&g_cnt[c], 1);
        g_csr_row[pos] = r;
        g_csr_norm[pos] = nv;
    }
}

// ---------------- 5. gather aggregation: warp per node ----------------------
__global__ void gather_kernel(const float* __restrict__ x) {
    int node = blockIdx.x * 8 + (threadIdx.x >> 5);
    if (node >= N_NODES) return;
    int lane = threadIdx.x & 31;
    const float4* x4 = (const float4*)x;

    float dv = g_dinv[node];
    float s = dv * dv;                 // self-loop norm
    float4 xv = x4[(size_t)node * 32 + lane];
    float4 acc = make_float4(xv.x * s, xv.y * s, xv.z * s, xv.w * s);

    int beg = g_off[node], end = g_off[node + 1];
    for (int k = beg; k < end; k++) {
        int r = g_csr_row[k];          // broadcast load across warp
        float nv = g_csr_norm[k];
        float4 v = x4[(size_t)r * 32 + lane];
        acc.x += nv * v.x; acc.y += nv * v.y;
        acc.z += nv * v.z; acc.w += nv * v.w;
    }
    ((float4*)g_xagg)[(size_t)node * 32 + lane] = acc;
}

// ---------------- 6. fused GEMM (xagg @ W) + ReLU + classifier --------------
// 256 threads = 8 warps; each warp computes 8 rows x 128 cols (4 cols/lane).
__global__ void final_kernel(const float* __restrict__ clsw,
                             const float* __restrict__ clsb,
                             float* __restrict__ out) {
    extern __shared__ float sh[];
    float* Ws = sh;                 // [128][128]
    float* xs = sh + C * C;         // 8 warps * 8 rows * 128
    int tid = threadIdx.x;

    const float4* Wg4 = (const float4*)g_W;
    float4* Ws4 = (float4*)Ws;
    for (int i = tid; i < C * C / 4; i += 256) Ws4[i] = Wg4[i];

    int warp = tid >> 5, lane = tid & 31;
    int row0 = blockIdx.x * 64 + warp * 8;
    float* myxs = xs + warp * (8 * C);
    #pragma unroll
    for (int r = 0; r < 8; r++) {
        int row = row0 + r;
        float4 v = make_float4(0.f, 0.f, 0.f, 0.f);
        if (row < N_NODES)
            v = *(const float4*)(g_xagg + (size_t)row * C + lane * 4);
        *(float4*)(myxs + r * C + lane * 4) = v;
    }
    __syncthreads();

    float4 acc[8];
    #pragma unroll
    for (int r = 0; r < 8; r++) acc[r] = make_float4(0.f, 0.f, 0.f, 0.f);

    #pragma unroll 2
    for (int k = 0; k < C; k++) {
        float4 wv = *(const float4*)(Ws + k * C + lane * 4);   // cols lane*4..+3
        #pragma unroll
        for (int r = 0; r < 8; r++) {
            float xv = myxs[r * C + k];                         // smem broadcast
            acc[r].x += xv * wv.x;
            acc[r].y += xv * wv.y;
            acc[r].z += xv * wv.z;
            acc[r].w += xv * wv.w;
        }
    }

    float4 cw = ((const float4*)clsw)[lane];
    float cb = clsb[0];
    #pragma unroll
    for (int r = 0; r < 8; r++) {
        float s = fmaxf(acc[r].x, 0.f) * cw.x + fmaxf(acc[r].y, 0.f) * cw.y
                + fmaxf(acc[r].z, 0.f) * cw.z + fmaxf(acc[r].w, 0.f) * cw.w;
        #pragma unroll
        for (int o = 16; o > 0; o >>= 1) s += __shfl_down_sync(0xffffffffu, s, o);
        if (lane == 0) {
            int row = row0 + r;
            if (row < N_NODES) out[row] = s + cb;
        }
    }
}

// ---------------- launcher ---------------------------------------------------
extern "C" void kernel_launch(void* const* d_in, const int* in_sizes, int n_in,
                              void* d_out, int out_size) {
    const float* x    = (const float*)d_in[0];
    const void*  ei   = d_in[1];                 // int32 or int64, detected on device
    const float* ew   = (const float*)d_in[2];
    const float* W0   = (const float*)d_in[3];
    const float* Wih  = (const float*)d_in[4];
    const float* Whh  = (const float*)d_in[5];
    const float* bih  = (const float*)d_in[6];
    const float* bhh  = (const float*)d_in[7];
    const float* clsw = (const float*)d_in[8];
    const float* clsb = (const float*)d_in[9];
    float* out = (float*)d_out;

    detect_kernel<<<1, 32>>>((const unsigned*)ei);
    gru_kernel<<<C, C>>>(W0, Wih, Whh, bih, bhh);
    deg_init<<<(N_NODES + 255) / 256, 256>>>();
    count_kernel<<<(N_EDGES + 255) / 256, 256>>>(ei, ew);
    dinv_kernel<<<(N_NODES + 255) / 256, 256>>>();
    scan_kernel<<<1, 1024>>>();
    fill_kernel<<<(N_EDGES + 255) / 256, 256>>>(ei, ew);
    gather_kernel<<<(N_NODES + 7) / 8, 256>>>(x);

    const int SMEM = (C * C + 8 * 8 * C) * (int)sizeof(float);   // 96 KB
    cudaFuncSetAttribute(final_kernel, cudaFuncAttributeMaxDynamicSharedMemorySize, SMEM);
    final_kernel<<<(N_NODES + 63) / 64, 256, SMEM>>>(clsw, clsb, out);
}

// round 4
// speedup vs baseline: 1.2697x; 1.2697x over previous
#include <cuda_runtime.h>

#define N_NODES 100000
#define N_EDGES 600000
#define C 128
#define SCAN_B 1024
#define N_SCAN_BLOCKS ((N_NODES + SCAN_B - 1) / SCAN_B)   // 98

// ---------------- scratch (static device globals; no runtime allocation) ----
__device__ __align__(16) float g_W[C * C];                    // evolved GCN weight
__device__ float g_dinv[N_NODES];                             // weighted deg -> dinv
__device__ int   g_cnt[N_NODES];                              // in-degree count / fill cursor
__device__ int   g_off[N_NODES + 1];                          // CSR offsets
__device__ int   g_bsum[N_SCAN_BLOCKS];                       // per-block scan totals
__device__ int   g_boff[N_SCAN_BLOCKS];                       // scanned block offsets
__device__ int   g_csr_row[N_EDGES];                          // CSR: source node per slot
__device__ float g_csr_norm[N_EDGES];                         // CSR: norm per slot
__device__ int   g_is64;                                      // edge_index dtype flag

// ---------------- 0. detect edge_index width (int32 vs int64) ---------------
__global__ void detect_kernel(const unsigned* __restrict__ ei_w) {
    int nz = 0;
    for (int i = threadIdx.x; i < 512; i += 32)
        if (ei_w[2 * i + 1] != 0u) nz++;
    #pragma unroll
    for (int o = 16; o > 0; o >>= 1) nz += __shfl_down_sync(0xffffffffu, nz, o);
    if (threadIdx.x == 0) g_is64 = (nz == 0) ? 1 : 0;
}

__device__ __forceinline__ int load_idx(const void* ei, long long pos, int is64) {
    return is64 ? (int)((const long long*)ei)[pos] : ((const int*)ei)[pos];
}

// ---------------- 1. GRU evolution of W0 (gate order r,z,n) -----------------
__global__ void gru_kernel(const float* __restrict__ W0,
                           const float* __restrict__ Wih,
                           const float* __restrict__ Whh,
                           const float* __restrict__ bih,
                           const float* __restrict__ bhh) {
    __shared__ float w0row[C];
    int i = blockIdx.x;
    int t = threadIdx.x;
    w0row[t] = W0[i * C + t];
    __syncthreads();

    float gir = bih[t], giz = bih[t + C], gin = bih[t + 2 * C];
    float ghr = bhh[t], ghz = bhh[t + C], ghn = bhh[t + 2 * C];
    const float* wr = Wih + (size_t)t * C;
    const float* wz = Wih + (size_t)(t + C) * C;
    const float* wn = Wih + (size_t)(t + 2 * C) * C;
    const float* hr = Whh + (size_t)t * C;
    const float* hz = Whh + (size_t)(t + C) * C;
    const float* hn = Whh + (size_t)(t + 2 * C) * C;
    #pragma unroll 4
    for (int k = 0; k < C; k++) {
        float a = w0row[k];
        gir += a * wr[k]; giz += a * wz[k]; gin += a * wn[k];
        ghr += a * hr[k]; ghz += a * hz[k]; ghn += a * hn[k];
    }
    float r    = 1.0f / (1.0f + expf(-(gir + ghr)));
    float z    = 1.0f / (1.0f + expf(-(giz + ghz)));
    float cand = tanhf(gin + r * ghn);
    g_W[i * C + t] = (1.0f - z) * cand + z * w0row[t];
}

// ---------------- 2. degree init + count ------------------------------------
__global__ void deg_init() {
    int i = blockIdx.x * blockDim.x + threadIdx.x;
    if (i < N_NODES) { g_dinv[i] = 1.0f; g_cnt[i] = 0; }   // self-loop weight
}

__global__ void count_kernel(const void* __restrict__ ei,
                             const float* __restrict__ ew) {
    int e = blockIdx.x * blockDim.x + threadIdx.x;
    if (e < N_EDGES) {
        int is64 = g_is64;
        int c = load_idx(ei, (long long)N_EDGES + e, is64);   // target
        atomicAdd(&g_dinv[c], ew[e]);    // weighted degree
        atomicAdd(&g_cnt[c], 1);         // in-degree for CSR
    }
}

// ---------------- 3. parallel exclusive scan (3 passes) ---------------------
// Pass A: per-block scan of counts -> g_off (local exclusive) + g_bsum.
//         Also converts g_dinv (degree) -> rsqrt(degree) elementwise.
__global__ void scan_a() {
    __shared__ int warpsum[32];
    int i = blockIdx.x * SCAN_B + threadIdx.x;
    int lane = threadIdx.x & 31, wid = threadIdx.x >> 5;
    int v = (i < N_NODES) ? g_cnt[i] : 0;
    if (i < N_NODES) g_dinv[i] = rsqrtf(g_dinv[i]);   // fold dinv here
    int incl = v;
    #pragma unroll
    for (int o = 1; o < 32; o <<= 1) {
        int t = __shfl_up_sync(0xffffffffu, incl, o);
        if (lane >= o) incl += t;
    }
    if (lane == 31) warpsum[wid] = incl;
    __syncthreads();
    if (wid == 0) {
        int ws = warpsum[lane];
        int wincl = ws;
        #pragma unroll
        for (int o = 1; o < 32; o <<= 1) {
            int t = __shfl_up_sync(0xffffffffu, wincl, o);
            if (lane >= o) wincl += t;
        }
        warpsum[lane] = wincl - ws;
        if (lane == 31) g_bsum[blockIdx.x] = wincl;
    }
    __syncthreads();
    if (i < N_NODES) g_off[i] = warpsum[wid] + incl - v;   // block-local exclusive
}

// Pass B: single block scans the 98 block sums (exclusive).
__global__ void scan_b() {   // <<<1, 128>>>
    __shared__ int warpsum[4];
    int lane = threadIdx.x & 31, wid = threadIdx.x >> 5;
    int v = (threadIdx.x < N_SCAN_BLOCKS) ? g_bsum[threadIdx.x] : 0;
    int incl = v;
    #pragma unroll
    for (int o = 1; o < 32; o <<= 1) {
        int t = __shfl_up_sync(0xffffffffu, incl, o);
        if (lane >= o) incl += t;
    }
    if (lane == 31) warpsum[wid] = incl;
    __syncthreads();
    int woff = 0;
    for (int w = 0; w < wid; w++) woff += warpsum[w];
    if (threadIdx.x < N_SCAN_BLOCKS) g_boff[threadIdx.x] = woff + incl - v;
}

// Pass C: add block offsets, zero fill cursors, set sentinel.
__global__ void scan_c() {
    int i = blockIdx.x * SCAN_B + threadIdx.x;
    if (i < N_NODES) {
        g_off[i] += g_boff[blockIdx.x];
        g_cnt[i] = 0;
    }
    if (i == 0) g_off[N_NODES] = N_EDGES;
}

// ---------------- 4. CSR fill (row + norm, contiguous per target) -----------
__global__ void fill_kernel(const void* __restrict__ ei,
                            const float* __restrict__ ew) {
    int e = blockIdx.x * blockDim.x + threadIdx.x;
    if (e < N_EDGES) {
        int is64 = g_is64;
        int r = load_idx(ei, e, is64);
        int c = load_idx(ei, (long long)N_EDGES + e, is64);
        float nv = g_dinv[r] * ew[e] * g_dinv[c];
        int pos = g_off[c] + atomicAdd(&g_cnt[c], 1);
        g_csr_row[pos] = r;
        g_csr_norm[pos] = nv;
    }
}

// ---------------- 5. fused gather + GEMM + ReLU + classifier ----------------
// 256 threads = 8 warps. Each warp: gathers 8 nodes' aggregated features
// directly into smem, then computes 8 rows x 128 cols of xagg @ W (4 cols/lane),
// then ReLU + classifier dot + warp reduce.
__global__ void final_kernel(const float* __restrict__ x,
                             const float* __restrict__ clsw,
                             const float* __restrict__ clsb,
                             float* __restrict__ out) {
    extern __shared__ float sh[];
    float* Ws = sh;                 // [128][128] = 64 KB
    float* xs = sh + C * C;         // 8 warps * 8 rows * 128 = 32 KB
    int tid = threadIdx.x;

    // stage W
    const float4* Wg4 = (const float4*)g_W;
    float4* Ws4 = (float4*)Ws;
    for (int i = tid; i < C * C / 4; i += 256) Ws4[i] = Wg4[i];

    int warp = tid >> 5, lane = tid & 31;
    int row0 = blockIdx.x * 64 + warp * 8;
    float* myxs = xs + warp * (8 * C);
    const float4* x4 = (const float4*)x;

    // gather: 8 nodes per warp, edges unrolled x4 for MLP
    #pragma unroll
    for (int r = 0; r < 8; r++) {
        int node = row0 + r;
        float4 acc = make_float4(0.f, 0.f, 0.f, 0.f);
        if (node < N_NODES) {
            float dv = g_dinv[node];
            float s = dv * dv;                 // self-loop norm
            float4 xv = x4[(size_t)node * 32 + lane];
            acc.x = xv.x * s; acc.y = xv.y * s; acc.z = xv.z * s; acc.w = xv.w * s;

            int k = g_off[node], end = g_off[node + 1];
            for (; k + 3 < end; k += 4) {
                int r0 = g_csr_row[k],     r1 = g_csr_row[k + 1];
                int r2 = g_csr_row[k + 2], r3 = g_csr_row[k + 3];
                float n0 = g_csr_norm[k],     n1 = g_csr_norm[k + 1];
                float n2 = g_csr_norm[k + 2], n3 = g_csr_norm[k + 3];
                float4 v0 = x4[(size_t)r0 * 32 + lane];
                float4 v1 = x4[(size_t)r1 * 32 + lane];
                float4 v2 = x4[(size_t)r2 * 32 + lane];
                float4 v3 = x4[(size_t)r3 * 32 + lane];
                acc.x += n0 * v0.x + n1 * v1.x + n2 * v2.x + n3 * v3.x;
                acc.y += n0 * v0.y + n1 * v1.y + n2 * v2.y + n3 * v3.y;
                acc.z += n0 * v0.z + n1 * v1.z + n2 * v2.z + n3 * v3.z;
                acc.w += n0 * v0.w + n1 * v1.w + n2 * v2.w + n3 * v3.w;
            }
            for (; k < end; k++) {
                int rr = g_csr_row[k];
                float nv = g_csr_norm[k];
                float4 v = x4[(size_t)rr * 32 + lane];
                acc.x += nv * v.x; acc.y += nv * v.y;
                acc.z += nv * v.z; acc.w += nv * v.w;
            }
        }
        *(float4*)(myxs + r * C + lane * 4) = acc;
    }
    __syncthreads();

    // GEMM: acc[r] = row r of (xs @ W), cols lane*4..lane*4+3
    float4 acc[8];
    #pragma unroll
    for (int r = 0; r < 8; r++) acc[r] = make_float4(0.f, 0.f, 0.f, 0.f);

    #pragma unroll 2
    for (int k = 0; k < C; k++) {
        float4 wv = *(const float4*)(Ws + k * C + lane * 4);
        #pragma unroll
        for (int r = 0; r < 8; r++) {
            float xv = myxs[r * C + k];
            acc[r].x += xv * wv.x;
            acc[r].y += xv * wv.y;
            acc[r].z += xv * wv.z;
            acc[r].w += xv * wv.w;
        }
    }

    float4 cw = ((const float4*)clsw)[lane];
    float cb = clsb[0];
    #pragma unroll
    for (int r = 0; r < 8; r++) {
        float s = fmaxf(acc[r].x, 0.f) * cw.x + fmaxf(acc[r].y, 0.f) * cw.y
                + fmaxf(acc[r].z, 0.f) * cw.z + fmaxf(acc[r].w, 0.f) * cw.w;
        #pragma unroll
        for (int o = 16; o > 0; o >>= 1) s += __shfl_down_sync(0xffffffffu, s, o);
        if (lane == 0) {
            int row = row0 + r;
            if (row < N_NODES) out[row] = s + cb;
        }
    }
}

// ---------------- launcher ---------------------------------------------------
extern "C" void kernel_launch(void* const* d_in, const int* in_sizes, int n_in,
                              void* d_out, int out_size) {
    const float* x    = (const float*)d_in[0];
    const void*  ei   = d_in[1];                 // int32 or int64, detected on device
    const float* ew   = (const float*)d_in[2];
    const float* W0   = (const float*)d_in[3];
    const float* Wih  = (const float*)d_in[4];
    const float* Whh  = (const float*)d_in[5];
    const float* bih  = (const float*)d_in[6];
    const float* bhh  = (const float*)d_in[7];
    const float* clsw = (const float*)d_in[8];
    const float* clsb = (const float*)d_in[9];
    float* out = (float*)d_out;

    detect_kernel<<<1, 32>>>((const unsigned*)ei);
    gru_kernel<<<C, C>>>(W0, Wih, Whh, bih, bhh);
    deg_init<<<(N_NODES + 255) / 256, 256>>>();
    count_kernel<<<(N_EDGES + 255) / 256, 256>>>(ei, ew);
    scan_a<<<N_SCAN_BLOCKS, SCAN_B>>>();
    scan_b<<<1, 128>>>();
    scan_c<<<N_SCAN_BLOCKS, SCAN_B>>>();
    fill_kernel<<<(N_EDGES + 255) / 256, 256>>>(ei, ew);

    const int SMEM = (C * C + 8 * 8 * C) * (int)sizeof(float);   // 96 KB
    cudaFuncSetAttribute(final_kernel, cudaFuncAttributeMaxDynamicSharedMemorySize, SMEM);
    final_kernel<<<(N_NODES + 63) / 64, 256, SMEM>>>(x, clsw, clsb, out);
}

// round 5
// speedup vs baseline: 1.5543x; 1.2241x over previous
#include <cuda_runtime.h>
#include <cuda_bf16.h>
#include <cstdint>

#define N_NODES 100000
#define N_EDGES 600000
#define C 128
#define SCAN_B 1024
#define N_SCAN_BLOCKS ((N_NODES + SCAN_B - 1) / SCAN_B)   // 98

// ---------------- scratch (static device globals) ---------------------------
__device__ __align__(16) float g_W[C * C];       // evolved GCN weight, W[k][n]
__device__ uint32_t g_Wth[C * (C / 2)];          // Wt hi bf16 pairs: [n][k/2]
__device__ uint32_t g_Wtl[C * (C / 2)];          // Wt lo bf16 pairs
__device__ float g_dinv[N_NODES];
__device__ int   g_cnt[N_NODES];
__device__ int   g_off[N_NODES + 1];
__device__ int   g_bsum[N_SCAN_BLOCKS];
__device__ int   g_boff[N_SCAN_BLOCKS];
__device__ int   g_csr_row[N_EDGES];
__device__ float g_csr_norm[N_EDGES];
__device__ int   g_is64;

// ---------------- 0. detect edge_index width --------------------------------
__global__ void detect_kernel(const unsigned* __restrict__ ei_w) {
    int nz = 0;
    for (int i = threadIdx.x; i < 512; i += 32)
        if (ei_w[2 * i + 1] != 0u) nz++;
    #pragma unroll
    for (int o = 16; o > 0; o >>= 1) nz += __shfl_down_sync(0xffffffffu, nz, o);
    if (threadIdx.x == 0) g_is64 = (nz == 0) ? 1 : 0;
}

__device__ __forceinline__ int load_idx(const void* ei, long long pos, int is64) {
    return is64 ? (int)((const long long*)ei)[pos] : ((const int*)ei)[pos];
}

// ---------------- 1. GRU evolution of W0 ------------------------------------
__global__ void gru_kernel(const float* __restrict__ W0,
                           const float* __restrict__ Wih,
                           const float* __restrict__ Whh,
                           const float* __restrict__ bih,
                           const float* __restrict__ bhh) {
    __shared__ float w0row[C];
    int i = blockIdx.x;
    int t = threadIdx.x;
    w0row[t] = W0[i * C + t];
    __syncthreads();

    float gir = bih[t], giz = bih[t + C], gin = bih[t + 2 * C];
    float ghr = bhh[t], ghz = bhh[t + C], ghn = bhh[t + 2 * C];
    const float* wr = Wih + (size_t)t * C;
    const float* wz = Wih + (size_t)(t + C) * C;
    const float* wn = Wih + (size_t)(t + 2 * C) * C;
    const float* hr = Whh + (size_t)t * C;
    const float* hz = Whh + (size_t)(t + C) * C;
    const float* hn = Whh + (size_t)(t + 2 * C) * C;
    #pragma unroll 4
    for (int k = 0; k < C; k++) {
        float a = w0row[k];
        gir += a * wr[k]; giz += a * wz[k]; gin += a * wn[k];
        ghr += a * hr[k]; ghz += a * hz[k]; ghn += a * hn[k];
    }
    float r    = 1.0f / (1.0f + expf(-(gir + ghr)));
    float z    = 1.0f / (1.0f + expf(-(giz + ghz)));
    float cand = tanhf(gin + r * ghn);
    g_W[i * C + t] = (1.0f - z) * cand + z * w0row[t];
}

// ---------------- 1b. split W into bf16 hi/lo, n-major, k-paired ------------
__global__ void wsplit_kernel() {    // <<<32, 256>>>
    int id = blockIdx.x * 256 + threadIdx.x;   // 8192 u32 slots
    if (id >= C * (C / 2)) return;
    int n = id >> 6, j = id & 63;              // k pair j -> k = 2j, 2j+1
    float w0 = g_W[(2 * j) * C + n];
    float w1 = g_W[(2 * j + 1) * C + n];
    __nv_bfloat162 h = __floats2bfloat162_rn(w0, w1);   // .x = w0 (low half)
    float2 hb = __bfloat1622float2(h);
    __nv_bfloat162 l = __floats2bfloat162_rn(w0 - hb.x, w1 - hb.y);
    g_Wth[id] = *(uint32_t*)&h;
    g_Wtl[id] = *(uint32_t*)&l;
}

// ---------------- 2. degree init + count ------------------------------------
__global__ void deg_init() {
    int i = blockIdx.x * blockDim.x + threadIdx.x;
    if (i < N_NODES) { g_dinv[i] = 1.0f; g_cnt[i] = 0; }
}

__global__ void count_kernel(const void* __restrict__ ei,
                             const float* __restrict__ ew) {
    int e = blockIdx.x * blockDim.x + threadIdx.x;
    if (e < N_EDGES) {
        int is64 = g_is64;
        int c = load_idx(ei, (long long)N_EDGES + e, is64);
        atomicAdd(&g_dinv[c], ew[e]);
        atomicAdd(&g_cnt[c], 1);
    }
}

// ---------------- 3. parallel exclusive scan (3 passes) ---------------------
__global__ void scan_a() {
    __shared__ int warpsum[32];
    int i = blockIdx.x * SCAN_B + threadIdx.x;
    int lane = threadIdx.x & 31, wid = threadIdx.x >> 5;
    int v = (i < N_NODES) ? g_cnt[i] : 0;
    if (i < N_NODES) g_dinv[i] = rsqrtf(g_dinv[i]);
    int incl = v;
    #pragma unroll
    for (int o = 1; o < 32; o <<= 1) {
        int t = __shfl_up_sync(0xffffffffu, incl, o);
        if (lane >= o) incl += t;
    }
    if (lane == 31) warpsum[wid] = incl;
    __syncthreads();
    if (wid == 0) {
        int ws = warpsum[lane];
        int wincl = ws;
        #pragma unroll
        for (int o = 1; o < 32; o <<= 1) {
            int t = __shfl_up_sync(0xffffffffu, wincl, o);
            if (lane >= o) wincl += t;
        }
        warpsum[lane] = wincl - ws;
        if (lane == 31) g_bsum[blockIdx.x] = wincl;
    }
    __syncthreads();
    if (i < N_NODES) g_off[i] = warpsum[wid] + incl - v;
}

__global__ void scan_b() {   // <<<1, 128>>>
    __shared__ int warpsum[4];
    int lane = threadIdx.x & 31, wid = threadIdx.x >> 5;
    int v = (threadIdx.x < N_SCAN_BLOCKS) ? g_bsum[threadIdx.x] : 0;
    int incl = v;
    #pragma unroll
    for (int o = 1; o < 32; o <<= 1) {
        int t = __shfl_up_sync(0xffffffffu, incl, o);
        if (lane >= o) incl += t;
    }
    if (lane == 31) warpsum[wid] = incl;
    __syncthreads();
    int woff = 0;
    for (int w = 0; w < wid; w++) woff += warpsum[w];
    if (threadIdx.x < N_SCAN_BLOCKS) g_boff[threadIdx.x] = woff + incl - v;
}

__global__ void scan_c() {
    int i = blockIdx.x * SCAN_B + threadIdx.x;
    if (i < N_NODES) {
        g_off[i] += g_boff[blockIdx.x];
        g_cnt[i] = 0;
    }
    if (i == 0) g_off[N_NODES] = N_EDGES;
}

// ---------------- 4. CSR fill ------------------------------------------------
__global__ void fill_kernel(const void* __restrict__ ei,
                            const float* __restrict__ ew) {
    int e = blockIdx.x * blockDim.x + threadIdx.x;
    if (e < N_EDGES) {
        int is64 = g_is64;
        int r = load_idx(ei, e, is64);
        int c = load_idx(ei, (long long)N_EDGES + e, is64);
        float nv = g_dinv[r] * ew[e] * g_dinv[c];
        int pos = g_off[c] + atomicAdd(&g_cnt[c], 1);
        g_csr_row[pos] = r;
        g_csr_norm[pos] = nv;
    }
}

// ---------------- 5. fused gather + bf16-split MMA + ReLU + cls -------------
// 256 threads = 8 warps, block tile = 64 rows x 128 cols.
// Warp w gathers local rows w*8..w*8+7. MMA: warp_m = w>>1 (16 rows),
// warp_n = w&1 (64 cols). Pair {2m,2m+1} syncs via named barrier m+1.
// A, B split into bf16 hi/lo; D += Ah*Bh + Ah*Bl + Al*Bh (fp32 accum).

__device__ __forceinline__ void mma_bf16(float& c0, float& c1, float& c2, float& c3,
                                         uint32_t a0, uint32_t a1, uint32_t a2, uint32_t a3,
                                         uint32_t b0, uint32_t b1) {
    asm volatile("mma.sync.aligned.m16n8k16.row.col.f32.bf16.bf16.f32 "
                 "{%0,%1,%2,%3}, {%4,%5,%6,%7}, {%8,%9}, {%0,%1,%2,%3};"
                 : "+f"(c0), "+f"(c1), "+f"(c2), "+f"(c3)
                 : "r"(a0), "r"(a1), "r"(a2), "r"(a3), "r"(b0), "r"(b1));
}

#define LDW 68   // padded row width in u32 (pairs of bf16) -> conflict-free

__global__ void __launch_bounds__(256, 2)
final_kernel(const float* __restrict__ x,
             const float* __restrict__ clsw,
             const float* __restrict__ clsb,
             float* __restrict__ out) {
    extern __shared__ char sh[];
    uint32_t* sWh = (uint32_t*)sh;                        // [128][LDW]
    uint32_t* sWl = sWh + C * LDW;                        // [128][LDW]
    uint32_t* xsh = sWl + C * LDW;                        // [64][LDW]
    uint32_t* xsl = xsh + 64 * LDW;                       // [64][LDW]
    float*    scw = (float*)(xsl + 64 * LDW);             // [128]
    float*    spart = scw + C;                            // [2][64]

    const int tid = threadIdx.x;
    const int warp = tid >> 5, lane = tid & 31;
    const int g = lane >> 2, t = lane & 3;

    // ---- stage W hi/lo (pad 64 -> LDW) + cls weights ----
    for (int i = tid; i < C * (C / 2); i += 256) {
        int n = i >> 6, j = i & 63;
        sWh[n * LDW + j] = g_Wth[i];
        sWl[n * LDW + j] = g_Wtl[i];
    }
    if (tid < C) scw[tid] = clsw[tid];
    __syncthreads();

    // ---- gather: 8 rows per warp, pack bf16 hi/lo into smem ----
    const int row0 = blockIdx.x * 64;
    const float4* x4 = (const float4*)x;
    #pragma unroll
    for (int r = 0; r < 8; r++) {
        int lrow = warp * 8 + r;
        int node = row0 + lrow;
        float4 acc = make_float4(0.f, 0.f, 0.f, 0.f);
        if (node < N_NODES) {
            float dv = g_dinv[node];
            float s = dv * dv;
            float4 xv = x4[(size_t)node * 32 + lane];
            acc.x = xv.x * s; acc.y = xv.y * s; acc.z = xv.z * s; acc.w = xv.w * s;
            int k = g_off[node], end = g_off[node + 1];
            for (; k + 3 < end; k += 4) {
                int r0 = g_csr_row[k],     r1 = g_csr_row[k + 1];
                int r2 = g_csr_row[k + 2], r3 = g_csr_row[k + 3];
                float n0 = g_csr_norm[k],     n1 = g_csr_norm[k + 1];
                float n2 = g_csr_norm[k + 2], n3 = g_csr_norm[k + 3];
                float4 v0 = x4[(size_t)r0 * 32 + lane];
                float4 v1 = x4[(size_t)r1 * 32 + lane];
                float4 v2 = x4[(size_t)r2 * 32 + lane];
                float4 v3 = x4[(size_t)r3 * 32 + lane];
                acc.x += n0 * v0.x + n1 * v1.x + n2 * v2.x + n3 * v3.x;
                acc.y += n0 * v0.y + n1 * v1.y + n2 * v2.y + n3 * v3.y;
                acc.z += n0 * v0.z + n1 * v1.z + n2 * v2.z + n3 * v3.z;
                acc.w += n0 * v0.w + n1 * v1.w + n2 * v2.w + n3 * v3.w;
            }
            for (; k < end; k++) {
                int rr = g_csr_row[k];
                float nv = g_csr_norm[k];
                float4 v = x4[(size_t)rr * 32 + lane];
                acc.x += nv * v.x; acc.y += nv * v.y;
                acc.z += nv * v.z; acc.w += nv * v.w;
            }
        }
        // pack: k = 4*lane + {0..3} -> u32 slots lane*2, lane*2+1
        __nv_bfloat162 h0 = __floats2bfloat162_rn(acc.x, acc.y);
        __nv_bfloat162 h1 = __floats2bfloat162_rn(acc.z, acc.w);
        float2 f0 = __bfloat1622float2(h0), f1 = __bfloat1622float2(h1);
        __nv_bfloat162 l0 = __floats2bfloat162_rn(acc.x - f0.x, acc.y - f0.y);
        __nv_bfloat162 l1 = __floats2bfloat162_rn(acc.z - f1.x, acc.w - f1.y);
        xsh[lrow * LDW + lane * 2]     = *(uint32_t*)&h0;
        xsh[lrow * LDW + lane * 2 + 1] = *(uint32_t*)&h1;
        xsl[lrow * LDW + lane * 2]     = *(uint32_t*)&l0;
        xsl[lrow * LDW + lane * 2 + 1] = *(uint32_t*)&l1;
    }

    // pair barrier: warps 2m, 2m+1 (tids 64m..64m+63)
    int m = warp >> 1, wn = warp & 1;
    asm volatile("bar.sync %0, %1;" :: "r"(m + 1), "r"(64) : "memory");

    // ---- MMA: 16 rows (m0..m0+15) x 64 cols (wn*64..+63), K = 128 ----
    const int m0 = m * 16;
    float acc[8][4];
    #pragma unroll
    for (int nt = 0; nt < 8; nt++)
        acc[nt][0] = acc[nt][1] = acc[nt][2] = acc[nt][3] = 0.f;

    #pragma unroll
    for (int kt = 0; kt < 8; kt++) {
        int abase = (m0 + g) * LDW + kt * 8 + t;
        uint32_t ah0 = xsh[abase],               ah1 = xsh[abase + 8 * LDW];
        uint32_t ah2 = xsh[abase + 4],           ah3 = xsh[abase + 8 * LDW + 4];
        uint32_t al0 = xsl[abase],               al1 = xsl[abase + 8 * LDW];
        uint32_t al2 = xsl[abase + 4],           al3 = xsl[abase + 8 * LDW + 4];
        #pragma unroll
        for (int nt = 0; nt < 8; nt++) {
            int n = wn * 64 + nt * 8 + g;
            int bbase = n * LDW + kt * 8 + t;
            uint32_t bh0 = sWh[bbase], bh1 = sWh[bbase + 4];
            uint32_t bl0 = sWl[bbase], bl1 = sWl[bbase + 4];
            mma_bf16(acc[nt][0], acc[nt][1], acc[nt][2], acc[nt][3],
                     ah0, ah1, ah2, ah3, bh0, bh1);
            mma_bf16(acc[nt][0], acc[nt][1], acc[nt][2], acc[nt][3],
                     ah0, ah1, ah2, ah3, bl0, bl1);
            mma_bf16(acc[nt][0], acc[nt][1], acc[nt][2], acc[nt][3],
                     al0, al1, al2, al3, bh0, bh1);
        }
    }

    // ---- epilogue: relu + cls partial dot, quad reduce ----
    float p0 = 0.f, p1 = 0.f;   // rows m0+g, m0+g+8
    #pragma unroll
    for (int nt = 0; nt < 8; nt++) {
        int col = wn * 64 + nt * 8 + 2 * t;
        float w0 = scw[col], w1 = scw[col + 1];
        p0 += fmaxf(acc[nt][0], 0.f) * w0 + fmaxf(acc[nt][1], 0.f) * w1;
        p1 += fmaxf(acc[nt][2], 0.f) * w0 + fmaxf(acc[nt][3], 0.f) * w1;
    }
    p0 += __shfl_xor_sync(0xffffffffu, p0, 1);
    p0 += __shfl_xor_sync(0xffffffffu, p0, 2);
    p1 += __shfl_xor_sync(0xffffffffu, p1, 1);
    p1 += __shfl_xor_sync(0xffffffffu, p1, 2);
    if (t == 0) {
        spart[wn * 64 + m0 + g]     = p0;
        spart[wn * 64 + m0 + g + 8] = p1;
    }
    __syncthreads();

    if (tid < 64) {
        int row = row0 + tid;
        if (row < N_NODES)
            out[row] = spart[tid] + spart[64 + tid] + clsb[0];
    }
}

// ---------------- launcher ---------------------------------------------------
extern "C" void kernel_launch(void* const* d_in, const int* in_sizes, int n_in,
                              void* d_out, int out_size) {
    const float* x    = (const float*)d_in[0];
    const void*  ei   = d_in[1];
    const float* ew   = (const float*)d_in[2];
    const float* W0   = (const float*)d_in[3];
    const float* Wih  = (const float*)d_in[4];
    const float* Whh  = (const float*)d_in[5];
    const float* bih  = (const float*)d_in[6];
    const float* bhh  = (const float*)d_in[7];
    const float* clsw = (const float*)d_in[8];
    const float* clsb = (const float*)d_in[9];
    float* out = (float*)d_out;

    detect_kernel<<<1, 32>>>((const unsigned*)ei);
    gru_kernel<<<C, C>>>(W0, Wih, Whh, bih, bhh);
    wsplit_kernel<<<32, 256>>>();
    deg_init<<<(N_NODES + 255) / 256, 256>>>();
    count_kernel<<<(N_EDGES + 255) / 256, 256>>>(ei, ew);
    scan_a<<<N_SCAN_BLOCKS, SCAN_B>>>();
    scan_b<<<1, 128>>>();
    scan_c<<<N_SCAN_BLOCKS, SCAN_B>>>();
    fill_kernel<<<(N_EDGES + 255) / 256, 256>>>(ei, ew);

    const int SMEM = (2 * C * LDW + 2 * 64 * LDW) * 4 + (C + 128) * 4;  // ~105.5 KB
    cudaFuncSetAttribute(final_kernel, cudaFuncAttributeMaxDynamicSharedMemorySize, SMEM);
    final_kernel<<<(N_NODES + 63) / 64, 256, SMEM>>>(x, clsw, clsb, out);
}